// round 8
// baseline (speedup 1.0000x reference)
#include <cuda_runtime.h>

#define NB 32
#define NPTS 512
#define NC 64
#define PIX (NC * NC)          // 4096
#define ROWS (NPTS + 1)        // 513
#define INV2S2 0.0078125f      // 1/(2*8^2)
#define BG_RATIO 0.15f

// Scratch: factorized exp tables (8 MB, L2-resident) + per-pixel softmax scale.
__device__ float g_Ex[NB][NPTS][NC];
__device__ float g_Ey[NB][NPTS][NC];
__device__ float g_inv[NB][PIX];   // 512 KB

// ---------------------------------------------------------------------------
// K1: Ex[b][n][j] = exp(-(x^2 - 2xc + c^2)/(2 sigma^2)), same for Ey.
// Matches the reference's expansion form for numerics parity.
// ---------------------------------------------------------------------------
__global__ void precompute_kernel(const float* __restrict__ points,
                                  const float* __restrict__ cood) {
    int idx = blockIdx.x * blockDim.x + threadIdx.x;   // NB*NPTS*NC = 1M
    int j = idx & (NC - 1);
    int n = (idx >> 6) & (NPTS - 1);
    int b = idx >> 15;

    float c = cood[j];
    float x = points[((b * NPTS + n) << 1) + 0];
    float y = points[((b * NPTS + n) << 1) + 1];

    float xd = x * x - 2.0f * x * c + c * c;
    float yd = y * y - 2.0f * y * c + c * c;

    g_Ex[b][n][j] = __expf(-xd * INV2S2);
    g_Ey[b][n][j] = __expf(-yd * INV2S2);
}

// ---------------------------------------------------------------------------
// K2: reduction pass. One CTA per (batch, 16-row i-tile), full 64-col width.
// Thread owns 4 contiguous j of one i row. Computes
//   S = sum_n Ey*Ex, M = max_n Ey*Ex  ->  inv = 1/(S + ebg), writes g_inv
// and the background row (row 512) of the output.
// ---------------------------------------------------------------------------
#define K2_SMEM ((NPTS * NC + NPTS * 16) * 4)   // 163840

__global__ __launch_bounds__(256, 1)
void reduce_kernel(const float* __restrict__ st_sizes,
                   float* __restrict__ out) {
    extern __shared__ float smem[];
    float* sEx = smem;                 // [NPTS][64]
    float* sEy = smem + NPTS * NC;     // [NPTS][16]

    int b  = blockIdx.x >> 2;
    int i0 = (blockIdx.x & 3) << 4;    // 0,16,32,48
    int t  = threadIdx.x;

    // Cooperative fill
    {
        const float4* src = (const float4*)&g_Ex[b][0][0];   // 8192 float4
        float4*       dst = (float4*)sEx;
#pragma unroll
        for (int k = 0; k < 32; k++)
            dst[t + 256 * k] = src[t + 256 * k];
        const float* eysrc = &g_Ey[b][0][i0];
        float4*      eydst = (float4*)sEy;                   // 2048 float4
#pragma unroll
        for (int k = 0; k < 8; k++) {
            int f = t + 256 * k;
            int n = f >> 2, q = f & 3;
            eydst[f] = *(const float4*)(eysrc + n * NC + q * 4);
        }
    }
    __syncthreads();

    int iloc = t >> 4;                 // 0..15
    int jq   = t & 15;                 // j = 4*jq .. +3

    const float4* exv = (const float4*)sEx + jq;   // row stride 16 float4

    float S0 = 0.f, S1 = 0.f, S2 = 0.f, S3 = 0.f;
    float M0 = 0.f, M1 = 0.f, M2 = 0.f, M3 = 0.f;

#pragma unroll 8
    for (int n = 0; n < NPTS; n++) {
        float  ey = sEy[n * 16 + iloc];
        float4 ex = exv[n * 16];
        float p0 = ey * ex.x, p1 = ey * ex.y, p2 = ey * ex.z, p3 = ey * ex.w;
        S0 += p0; S1 += p1; S2 += p2; S3 += p3;
        M0 = fmaxf(M0, p0); M1 = fmaxf(M1, p1);
        M2 = fmaxf(M2, p2); M3 = fmaxf(M3, p3);
    }

    float d = st_sizes[b] * BG_RATIO;

    float M[4] = {M0, M1, M2, M3};
    float S[4] = {S0, S1, S2, S3};
    float4 iv, pb;
    float* ivp = &iv.x; float* pbp = &pb.x;
#pragma unroll
    for (int k = 0; k < 4; k++) {
        float m    = fmaxf(M[k], 1e-35f);
        float mind = fmaxf(-128.0f * __logf(m), 0.0f);  // 2*sigma^2 = 128
        float bd   = d - sqrtf(mind);
        float ebg  = __expf(-(bd * bd) * INV2S2);
        ivp[k] = 1.0f / (S[k] + ebg);
        pbp[k] = ebg * ivp[k];
    }

    int px = (i0 + iloc) * NC + jq * 4;
    *(float4*)&g_inv[b][px] = iv;
    *(float4*)(out + (size_t)b * ROWS * PIX + (size_t)NPTS * PIX + px) = pb;
}

// ---------------------------------------------------------------------------
// K3: pure streaming pass. No smem, no syncs, high occupancy.
// Warp owns 4 output rows (b, n..n+3). For each n: lane's 4 ex values stay in
// registers for the whole row; ey is a warp-broadcast L1-hit load; inv[b]
// (16 KB) is L1-resident. One STG.128 per lane-iter.
//   lane < 16 : i = 2*it,   j = 4*lane
//   lane >= 16: i = 2*it+1, j = 4*(lane-16)
// -> per iter, warp reads inv/writes out at [it*128 + lane*4 .. +3]: fully
//    coalesced 512B.
// ---------------------------------------------------------------------------
__global__ __launch_bounds__(256)
void stream_kernel(float* __restrict__ out) {
    int b     = blockIdx.x >> 4;            // 32
    int chunk = blockIdx.x & 15;            // 16 chunks of 32 n
    int w     = threadIdx.x >> 5;
    int lane  = threadIdx.x & 31;
    int half  = lane >> 4;
    int jq    = lane & 15;

    const float* invb = g_inv[b];
    float*       outb = out + (size_t)b * ROWS * PIX;
    int n0 = chunk * 32 + w * 4;

#pragma unroll
    for (int nn = 0; nn < 4; nn++) {
        int n = n0 + nn;
        float4 ex = *(const float4*)&g_Ex[b][n][jq << 2];
        const float* eyrow = &g_Ey[b][n][0];
        float*       orow  = outb + (size_t)n * PIX + (lane << 2);
        const float* invp  = invb + (lane << 2);

#pragma unroll 8
        for (int it = 0; it < 32; it++) {
            float2 eyp = *(const float2*)(eyrow + (it << 1));
            float  ey  = half ? eyp.y : eyp.x;
            float4 iv  = *(const float4*)(invp + (it << 7));
            float4 o;
            o.x = ey * ex.x * iv.x;
            o.y = ey * ex.y * iv.y;
            o.z = ey * ex.z * iv.z;
            o.w = ey * ex.w * iv.w;
            *(float4*)(orow + (it << 7)) = o;
        }
    }
}

// ---------------------------------------------------------------------------
extern "C" void kernel_launch(void* const* d_in, const int* in_sizes, int n_in,
                              void* d_out, int out_size) {
    const float* points   = (const float*)d_in[0];
    const float* st_sizes = (const float*)d_in[1];
    const float* cood     = (const float*)d_in[2];
    float*       out      = (float*)d_out;

    cudaFuncSetAttribute(reduce_kernel,
                         cudaFuncAttributeMaxDynamicSharedMemorySize,
                         K2_SMEM);

    precompute_kernel<<<(NB * NPTS * NC) / 256, 256>>>(points, cood);
    reduce_kernel<<<NB * 4, 256, K2_SMEM>>>(st_sizes, out);
    stream_kernel<<<NB * 16, 256>>>(out);
}

// round 9
// speedup vs baseline: 1.3795x; 1.3795x over previous
#include <cuda_runtime.h>

#define NB 32
#define NPTS 512
#define NC 64
#define PIX (NC * NC)          // 4096
#define ROWS (NPTS + 1)        // 513
#define INV2S2 0.0078125f      // 1/(2*8^2)
#define BG_RATIO 0.15f

// Scratch: factorized exp tables. 2 * 32 * 512 * 64 * 4B = 8 MB (L2-resident).
__device__ float g_Ex[NB][NPTS][NC];
__device__ float g_Ey[NB][NPTS][NC];

// ---------------------------------------------------------------------------
// K1: Ex[b][n][j] = exp(-(x^2 - 2xc + c^2)/(2 sigma^2)), same for Ey.
// Matches the reference's expansion form for numerics parity.
// ---------------------------------------------------------------------------
__global__ void precompute_kernel(const float* __restrict__ points,
                                  const float* __restrict__ cood) {
    int idx = blockIdx.x * blockDim.x + threadIdx.x;   // NB*NPTS*NC = 1M
    int j = idx & (NC - 1);
    int n = (idx >> 6) & (NPTS - 1);
    int b = idx >> 15;

    float c = cood[j];
    float x = points[((b * NPTS + n) << 1) + 0];
    float y = points[((b * NPTS + n) << 1) + 1];

    float xd = x * x - 2.0f * x * c + c * c;
    float yd = y * y - 2.0f * y * c + c * c;

    g_Ex[b][n][j] = __expf(-xd * INV2S2);
    g_Ey[b][n][j] = __expf(-yd * INV2S2);
}

// ---------------------------------------------------------------------------
// K2: fused softmax with a 2-tile chained pipeline per CTA.
// CTA = (batch b, chain c): tile0 = i rows [16c, 16c+8), tile1 = [16c+8, 16c+16).
// 256 threads: warp w owns i-row (w), lane jp owns j = {2jp, 2jp+1}.
// smem: Ex[512][64] (shared by both tiles) + Ey0[512][8] + Ey1[512][8].
//
//  A: fill smem; reduce tile0 (S,M); finalize inv/bg for tile0.
//  B: for n: store tile0 row n AND accumulate tile1 (shared ex load).
//  C: finalize tile1; store tile1 rows.
// Softmax identity: out = Ey*Ex / (S + ebg); bg row = ebg/(S+ebg);
// min_dis = max(0, -2s^2 ln(max_n Ey*Ex)). No max-shift needed (exact quotient).
// ---------------------------------------------------------------------------
#define SMEM_BYTES ((NPTS * NC + NPTS * 16) * 4)   // 163840

__global__ __launch_bounds__(256, 1)
void post_prob_kernel(const float* __restrict__ st_sizes,
                      float* __restrict__ out) {
    extern __shared__ float smem[];
    float* sEx  = smem;                   // [512][64]
    float* sEy0 = smem + NPTS * NC;       // [512][8]
    float* sEy1 = sEy0 + NPTS * 8;        // [512][8]

    int b  = blockIdx.x >> 2;
    int c  = blockIdx.x & 3;
    int i0 = c << 4;                      // tile0 base row; tile1 = i0+8
    int t  = threadIdx.x;
    int iloc = t >> 5;                    // warp id = i row within tile (0..7)
    int jp   = t & 31;                    // j pair index

    // ---- fill smem ----
    {
        const float4* src = (const float4*)&g_Ex[b][0][0];   // 8192 float4
        float4*       dst = (float4*)sEx;
#pragma unroll
        for (int k = 0; k < 32; k++)
            dst[t + 256 * k] = src[t + 256 * k];

        // Ey tiles: per n, 8 floats at col i0 (tile0) and i0+8 (tile1)
#pragma unroll
        for (int k = 0; k < 4; k++) {
            int f = t + 256 * k;          // 0..1023
            int n = f >> 1, h = f & 1;    // h: which float4 half of the 8
            ((float4*)sEy0)[n * 2 + h] =
                *(const float4*)&g_Ey[b][n][i0 + h * 4];
            ((float4*)sEy1)[n * 2 + h] =
                *(const float4*)&g_Ey[b][n][i0 + 8 + h * 4];
        }
    }
    __syncthreads();

    const float2* exv = (const float2*)sEx + jp;   // row stride 32 float2

    // ---- Phase A: reduce tile0 ----
    float S0 = 0.f, S1 = 0.f, M0 = 0.f, M1 = 0.f;
#pragma unroll 8
    for (int n = 0; n < NPTS; n++) {
        float  ey = sEy0[n * 8 + iloc];
        float2 ex = exv[n * 32];
        float p0 = ey * ex.x, p1 = ey * ex.y;
        S0 += p0; S1 += p1;
        M0 = fmaxf(M0, p0); M1 = fmaxf(M1, p1);
    }

    float d = st_sizes[b] * BG_RATIO;

    float inv0x, inv0y;
    {
        float m0  = fmaxf(M0, 1e-35f);
        float m1  = fmaxf(M1, 1e-35f);
        float mn0 = fmaxf(-128.0f * __logf(m0), 0.0f);  // 2*sigma^2 = 128
        float mn1 = fmaxf(-128.0f * __logf(m1), 0.0f);
        float bd0 = d - sqrtf(mn0);
        float bd1 = d - sqrtf(mn1);
        float eb0 = __expf(-(bd0 * bd0) * INV2S2);
        float eb1 = __expf(-(bd1 * bd1) * INV2S2);
        inv0x = 1.0f / (S0 + eb0);
        inv0y = 1.0f / (S1 + eb1);
        float* bg = out + (size_t)b * ROWS * PIX + (size_t)NPTS * PIX
                        + (i0 + iloc) * NC + jp * 2;
        *(float2*)bg = make_float2(eb0 * inv0x, eb1 * inv0y);
    }

    float* outb  = out + (size_t)b * ROWS * PIX;
    float* orow0 = outb + (i0 + iloc) * NC + jp * 2;

    // ---- Phase B: store tile0 + reduce tile1 (shared ex load) ----
    float T0 = 0.f, T1 = 0.f, N0 = 0.f, N1 = 0.f;
#pragma unroll 4
    for (int n = 0; n < NPTS; n++) {
        float2 ex  = exv[n * 32];
        float  ey0 = sEy0[n * 8 + iloc];
        float  ey1 = sEy1[n * 8 + iloc];

        float2 o;
        o.x = ey0 * ex.x * inv0x;
        o.y = ey0 * ex.y * inv0y;
        *(float2*)(orow0 + (size_t)n * PIX) = o;

        float p0 = ey1 * ex.x, p1 = ey1 * ex.y;
        T0 += p0; T1 += p1;
        N0 = fmaxf(N0, p0); N1 = fmaxf(N1, p1);
    }

    // ---- finalize tile1 ----
    float inv1x, inv1y;
    {
        float m0  = fmaxf(N0, 1e-35f);
        float m1  = fmaxf(N1, 1e-35f);
        float mn0 = fmaxf(-128.0f * __logf(m0), 0.0f);
        float mn1 = fmaxf(-128.0f * __logf(m1), 0.0f);
        float bd0 = d - sqrtf(mn0);
        float bd1 = d - sqrtf(mn1);
        float eb0 = __expf(-(bd0 * bd0) * INV2S2);
        float eb1 = __expf(-(bd1 * bd1) * INV2S2);
        inv1x = 1.0f / (T0 + eb0);
        inv1y = 1.0f / (T1 + eb1);
        float* bg = outb + (size_t)NPTS * PIX + (i0 + 8 + iloc) * NC + jp * 2;
        *(float2*)bg = make_float2(eb0 * inv1x, eb1 * inv1y);
    }

    float* orow1 = outb + (i0 + 8 + iloc) * NC + jp * 2;

    // ---- Phase C: store tile1 ----
#pragma unroll 8
    for (int n = 0; n < NPTS; n++) {
        float2 ex  = exv[n * 32];
        float  ey1 = sEy1[n * 8 + iloc];
        float2 o;
        o.x = ey1 * ex.x * inv1x;
        o.y = ey1 * ex.y * inv1y;
        *(float2*)(orow1 + (size_t)n * PIX) = o;
    }
}

// ---------------------------------------------------------------------------
extern "C" void kernel_launch(void* const* d_in, const int* in_sizes, int n_in,
                              void* d_out, int out_size) {
    const float* points   = (const float*)d_in[0];
    const float* st_sizes = (const float*)d_in[1];
    const float* cood     = (const float*)d_in[2];
    float*       out      = (float*)d_out;

    cudaFuncSetAttribute(post_prob_kernel,
                         cudaFuncAttributeMaxDynamicSharedMemorySize,
                         SMEM_BYTES);

    precompute_kernel<<<(NB * NPTS * NC) / 256, 256>>>(points, cood);
    post_prob_kernel<<<NB * 4, 256, SMEM_BYTES>>>(st_sizes, out);
}

// round 10
// speedup vs baseline: 1.4897x; 1.0799x over previous
#include <cuda_runtime.h>

#define NB 32
#define NPTS 512
#define NC 64
#define PIX (NC * NC)          // 4096
#define ROWS (NPTS + 1)        // 513
#define INV2S2 0.0078125f      // 1/(2*8^2)
#define BG_RATIO 0.15f

// ---------------------------------------------------------------------------
// Single fused kernel. CTA = (batch b, chain c): tile0 = i rows [16c,16c+8),
// tile1 = [16c+8,16c+16). 256 threads: warp w = i-row, lane jp = j pair.
//
// Build phase (replaces the old precompute kernel + smem fill):
//   thread t computes rows n = t, t+256 of
//     sEx[n][j]  = exp(-(x^2-2xc_j+c_j^2)/128)        (64 cols)
//     sEy0[n][k] = exp(-(y^2-2yc+c^2)/128) at cols i0..i0+7
//     sEy1[n][k] = same at cols i0+8..i0+15
//   directly from points[b] (4 KB) + cood (256 B). No global scratch.
//
//  A: reduce tile0 (S,M); finalize inv/bg.
//  B: store tile0 row n AND accumulate tile1 (shared ex load).
//  C: finalize tile1; store tile1 rows.
// Softmax identity: out = Ey*Ex/(S+ebg); bg = ebg/(S+ebg);
// min_dis = max(0, -128 ln(max_n Ey*Ex)). Exact quotient, no max-shift.
// ---------------------------------------------------------------------------
#define SMEM_BYTES ((NPTS * NC + NPTS * 16 + NC) * 4)   // 164096

__global__ __launch_bounds__(256, 1)
void post_prob_kernel(const float* __restrict__ points,
                      const float* __restrict__ st_sizes,
                      const float* __restrict__ cood,
                      float* __restrict__ out) {
    extern __shared__ float smem[];
    float* sEx   = smem;                   // [512][64]
    float* sEy0  = smem + NPTS * NC;       // [512][8]
    float* sEy1  = sEy0 + NPTS * 8;        // [512][8]
    float* sCood = sEy1 + NPTS * 8;        // [64]

    int b  = blockIdx.x >> 2;
    int c  = blockIdx.x & 3;
    int i0 = c << 4;                       // tile0 base; tile1 = i0+8
    int t  = threadIdx.x;
    int iloc = t >> 5;                     // warp id (0..7) = row in tile
    int jp   = t & 31;                     // j pair index

    if (t < NC) sCood[t] = cood[t];
    __syncthreads();

    // ---- build phase: compute Ex / Ey windows in smem ----
#pragma unroll
    for (int r = 0; r < 2; r++) {
        int n = t + (r << 8);
        float2 pt = *(const float2*)(points + ((size_t)b * NPTS + n) * 2);
        float x = pt.x, y = pt.y;
        float x2 = x * x, y2 = y * y;
        float tx = 2.0f * x, ty = 2.0f * y;

        // Ex row: 16 float4 stores, rotated start to avoid bank conflicts
#pragma unroll
        for (int q = 0; q < 16; q++) {
            int jb = ((q + t) & 15) << 2;
            float4 cv = *(const float4*)&sCood[jb];
            float4 e;
            e.x = __expf(-(x2 - tx * cv.x + cv.x * cv.x) * INV2S2);
            e.y = __expf(-(x2 - tx * cv.y + cv.y * cv.y) * INV2S2);
            e.z = __expf(-(x2 - tx * cv.z + cv.z * cv.z) * INV2S2);
            e.w = __expf(-(x2 - tx * cv.w + cv.w * cv.w) * INV2S2);
            *(float4*)&sEx[n * NC + jb] = e;
        }
        // Ey windows: 2 float4 each
#pragma unroll
        for (int h = 0; h < 2; h++) {
            float4 cv = *(const float4*)&sCood[i0 + (h << 2)];
            float4 e;
            e.x = __expf(-(y2 - ty * cv.x + cv.x * cv.x) * INV2S2);
            e.y = __expf(-(y2 - ty * cv.y + cv.y * cv.y) * INV2S2);
            e.z = __expf(-(y2 - ty * cv.z + cv.z * cv.z) * INV2S2);
            e.w = __expf(-(y2 - ty * cv.w + cv.w * cv.w) * INV2S2);
            *(float4*)&sEy0[n * 8 + (h << 2)] = e;

            float4 cw = *(const float4*)&sCood[i0 + 8 + (h << 2)];
            float4 f;
            f.x = __expf(-(y2 - ty * cw.x + cw.x * cw.x) * INV2S2);
            f.y = __expf(-(y2 - ty * cw.y + cw.y * cw.y) * INV2S2);
            f.z = __expf(-(y2 - ty * cw.z + cw.z * cw.z) * INV2S2);
            f.w = __expf(-(y2 - ty * cw.w + cw.w * cw.w) * INV2S2);
            *(float4*)&sEy1[n * 8 + (h << 2)] = f;
        }
    }
    __syncthreads();

    const float2* exv = (const float2*)sEx + jp;   // row stride 32 float2

    // ---- Phase A: reduce tile0 ----
    float S0 = 0.f, S1 = 0.f, M0 = 0.f, M1 = 0.f;
#pragma unroll 8
    for (int n = 0; n < NPTS; n++) {
        float  ey = sEy0[n * 8 + iloc];
        float2 ex = exv[n * 32];
        float p0 = ey * ex.x, p1 = ey * ex.y;
        S0 += p0; S1 += p1;
        M0 = fmaxf(M0, p0); M1 = fmaxf(M1, p1);
    }

    float d = st_sizes[b] * BG_RATIO;

    float inv0x, inv0y;
    {
        float m0  = fmaxf(M0, 1e-35f);
        float m1  = fmaxf(M1, 1e-35f);
        float mn0 = fmaxf(-128.0f * __logf(m0), 0.0f);  // 2*sigma^2 = 128
        float mn1 = fmaxf(-128.0f * __logf(m1), 0.0f);
        float bd0 = d - sqrtf(mn0);
        float bd1 = d - sqrtf(mn1);
        float eb0 = __expf(-(bd0 * bd0) * INV2S2);
        float eb1 = __expf(-(bd1 * bd1) * INV2S2);
        inv0x = 1.0f / (S0 + eb0);
        inv0y = 1.0f / (S1 + eb1);
        float* bg = out + (size_t)b * ROWS * PIX + (size_t)NPTS * PIX
                        + (i0 + iloc) * NC + jp * 2;
        *(float2*)bg = make_float2(eb0 * inv0x, eb1 * inv0y);
    }

    float* outb  = out + (size_t)b * ROWS * PIX;
    float* orow0 = outb + (i0 + iloc) * NC + jp * 2;

    // ---- Phase B: store tile0 + reduce tile1 (shared ex load) ----
    float T0 = 0.f, T1 = 0.f, N0 = 0.f, N1 = 0.f;
#pragma unroll 4
    for (int n = 0; n < NPTS; n++) {
        float2 ex  = exv[n * 32];
        float  ey0 = sEy0[n * 8 + iloc];
        float  ey1 = sEy1[n * 8 + iloc];

        float2 o;
        o.x = ey0 * ex.x * inv0x;
        o.y = ey0 * ex.y * inv0y;
        *(float2*)(orow0 + (size_t)n * PIX) = o;

        float p0 = ey1 * ex.x, p1 = ey1 * ex.y;
        T0 += p0; T1 += p1;
        N0 = fmaxf(N0, p0); N1 = fmaxf(N1, p1);
    }

    // ---- finalize tile1 ----
    float inv1x, inv1y;
    {
        float m0  = fmaxf(N0, 1e-35f);
        float m1  = fmaxf(N1, 1e-35f);
        float mn0 = fmaxf(-128.0f * __logf(m0), 0.0f);
        float mn1 = fmaxf(-128.0f * __logf(m1), 0.0f);
        float bd0 = d - sqrtf(mn0);
        float bd1 = d - sqrtf(mn1);
        float eb0 = __expf(-(bd0 * bd0) * INV2S2);
        float eb1 = __expf(-(bd1 * bd1) * INV2S2);
        inv1x = 1.0f / (T0 + eb0);
        inv1y = 1.0f / (T1 + eb1);
        float* bg = outb + (size_t)NPTS * PIX + (i0 + 8 + iloc) * NC + jp * 2;
        *(float2*)bg = make_float2(eb0 * inv1x, eb1 * inv1y);
    }

    float* orow1 = outb + (i0 + 8 + iloc) * NC + jp * 2;

    // ---- Phase C: store tile1 ----
#pragma unroll 8
    for (int n = 0; n < NPTS; n++) {
        float2 ex  = exv[n * 32];
        float  ey1 = sEy1[n * 8 + iloc];
        float2 o;
        o.x = ey1 * ex.x * inv1x;
        o.y = ey1 * ex.y * inv1y;
        *(float2*)(orow1 + (size_t)n * PIX) = o;
    }
}

// ---------------------------------------------------------------------------
extern "C" void kernel_launch(void* const* d_in, const int* in_sizes, int n_in,
                              void* d_out, int out_size) {
    const float* points   = (const float*)d_in[0];
    const float* st_sizes = (const float*)d_in[1];
    const float* cood     = (const float*)d_in[2];
    float*       out      = (float*)d_out;

    cudaFuncSetAttribute(post_prob_kernel,
                         cudaFuncAttributeMaxDynamicSharedMemorySize,
                         SMEM_BYTES);

    post_prob_kernel<<<NB * 4, 256, SMEM_BYTES>>>(points, st_sizes, cood, out);
}